// round 14
// baseline (speedup 1.0000x reference)
#include <cuda_runtime.h>
#include <cuda_bf16.h>
#include <math.h>

#define Bb 4
#define Ss 2048
#define Dd 1024
#define Hh 16
#define DK 64
#define Mm (Bb*Ss)

// Scratch (no cudaMalloc allowed)
__device__ float g_q[Bb*Hh*Ss*DK];    // [b][h][s][d]
__device__ float g_k[Bb*Hh*Ss*DK];    // [b][h][s][d]
__device__ float g_v[Bb*Hh*Ss*DK];    // [b][h][d][s]  (transposed for PV MMA)
__device__ float g_att[Bb*Ss*Dd];     // [b][s][h*64+d]

// ---------------------------------------------------------------------------
__device__ __forceinline__ void mma16816(float* c, const unsigned* a, const unsigned* b)
{
    asm volatile(
        "mma.sync.aligned.m16n8k16.row.col.f32.bf16.bf16.f32 "
        "{%0,%1,%2,%3}, {%4,%5,%6,%7}, {%8,%9}, {%0,%1,%2,%3};\n"
        : "+f"(c[0]), "+f"(c[1]), "+f"(c[2]), "+f"(c[3])
        : "r"(a[0]), "r"(a[1]), "r"(a[2]), "r"(a[3]), "r"(b[0]), "r"(b[1]));
}

__device__ __forceinline__ void ldsm4(unsigned& r0, unsigned& r1, unsigned& r2, unsigned& r3,
                                      unsigned saddr)
{
    asm volatile("ldmatrix.sync.aligned.m8n8.x4.shared.b16 {%0,%1,%2,%3}, [%4];\n"
                 : "=r"(r0), "=r"(r1), "=r"(r2), "=r"(r3) : "r"(saddr));
}

// split x,y into bf16 hi pair + bf16 lo pair (packed b32 each, x in low half)
__device__ __forceinline__ void splitpack(float x, float y, unsigned& hi, unsigned& lo)
{
    __nv_bfloat162 h2 = __floats2bfloat162_rn(x, y);
    float hx = __bfloat162float(h2.x), hy = __bfloat162float(h2.y);
    __nv_bfloat162 l2 = __floats2bfloat162_rn(x - hx, y - hy);
    hi = *reinterpret_cast<unsigned*>(&h2);
    lo = *reinterpret_cast<unsigned*>(&l2);
}

// ---------------------------------------------------------------------------
// Split-precision bf16 tensor-core GEMM (+ register prefetch of next k-tile)
// C[m][n] = sum_k A[m][k] * W[n][k];  C ≈ Ah*Wh + Al*Wh + Ah*Wl
// Block 128x128, BK=32, 8 warps, warp tile 32x64.
// mode 0: QKV (z selects W/dst; Q,K -> [b][h][s][d]; V -> [b][h][d][s])
// mode 1: out-proj (A = g_att via device symbol), linear epilogue.
// ---------------------------------------------------------------------------
#define LDS_STRIDE 36   // halves per row (32 + 4 pad)

__global__ __launch_bounds__(256)
void gemm_bf16s(const float* __restrict__ Ain,
                const float* __restrict__ w0, const float* __restrict__ w1,
                const float* __restrict__ w2, float* __restrict__ outp, int mode)
{
    __shared__ __nv_bfloat16 Ah[128 * LDS_STRIDE];
    __shared__ __nv_bfloat16 Al[128 * LDS_STRIDE];
    __shared__ __nv_bfloat16 Bh[128 * LDS_STRIDE];
    __shared__ __nv_bfloat16 Bl[128 * LDS_STRIDE];

    const float* A;
    const float* W;
    float* dst;
    if (mode == 0) {
        A   = Ain;
        W   = (blockIdx.z == 0) ? w0  : (blockIdx.z == 1) ? w1  : w2;
        dst = (blockIdx.z == 0) ? g_q : (blockIdx.z == 1) ? g_k : g_v;
    } else {
        A = g_att;
        W = w0; dst = outp;
    }

    const int m0 = blockIdx.x * 128, n0 = blockIdx.y * 128;
    const int tid = threadIdx.x;
    const int wid = tid >> 5, lane = tid & 31;
    const int wm = (wid & 3) * 32;
    const int wn = (wid >> 2) * 64;
    const int lr = lane >> 2;
    const int lk = (lane & 3) * 2;

    float acc[2][8][4];
#pragma unroll
    for (int i = 0; i < 2; i++)
#pragma unroll
        for (int j = 0; j < 8; j++)
#pragma unroll
            for (int q = 0; q < 4; q++) acc[i][j][q] = 0.0f;

    // prefetch registers for current k-tile
    float4 va[4], vb[4];
#pragma unroll
    for (int l = 0; l < 4; l++) {
        int fi = tid + l * 256;
        int row = fi >> 3, kq = fi & 7;
        va[l] = *(const float4*)&A[(size_t)(m0 + row) * Dd + kq * 4];
        vb[l] = *(const float4*)&W[(size_t)(n0 + row) * Dd + kq * 4];
    }

    for (int kt = 0; kt < Dd; kt += 32) {
        // ---- convert + split staged regs into smem ----
#pragma unroll
        for (int l = 0; l < 4; l++) {
            int fi = tid + l * 256;
            int row = fi >> 3, kq = fi & 7;
            int off = row * LDS_STRIDE + kq * 4;
            unsigned h0, l0, h1, l1;
            splitpack(va[l].x, va[l].y, h0, l0);
            splitpack(va[l].z, va[l].w, h1, l1);
            *(uint2*)&Ah[off] = make_uint2(h0, h1);
            *(uint2*)&Al[off] = make_uint2(l0, l1);
            splitpack(vb[l].x, vb[l].y, h0, l0);
            splitpack(vb[l].z, vb[l].w, h1, l1);
            *(uint2*)&Bh[off] = make_uint2(h0, h1);
            *(uint2*)&Bl[off] = make_uint2(l0, l1);
        }
        __syncthreads();

        // ---- issue gmem loads for next k-tile (overlap with MMA) ----
        if (kt + 32 < Dd) {
#pragma unroll
            for (int l = 0; l < 4; l++) {
                int fi = tid + l * 256;
                int row = fi >> 3, kq = fi & 7;
                va[l] = *(const float4*)&A[(size_t)(m0 + row) * Dd + kt + 32 + kq * 4];
                vb[l] = *(const float4*)&W[(size_t)(n0 + row) * Dd + kt + 32 + kq * 4];
            }
        }

#pragma unroll
        for (int kc = 0; kc < 32; kc += 16) {
            unsigned ah[2][4], al[2][4];
#pragma unroll
            for (int mt = 0; mt < 2; mt++) {
                int r = wm + mt * 16 + lr;
                int kb = kc + lk;
                ah[mt][0] = *(const unsigned*)&Ah[r * LDS_STRIDE + kb];
                ah[mt][1] = *(const unsigned*)&Ah[(r + 8) * LDS_STRIDE + kb];
                ah[mt][2] = *(const unsigned*)&Ah[r * LDS_STRIDE + kb + 8];
                ah[mt][3] = *(const unsigned*)&Ah[(r + 8) * LDS_STRIDE + kb + 8];
                al[mt][0] = *(const unsigned*)&Al[r * LDS_STRIDE + kb];
                al[mt][1] = *(const unsigned*)&Al[(r + 8) * LDS_STRIDE + kb];
                al[mt][2] = *(const unsigned*)&Al[r * LDS_STRIDE + kb + 8];
                al[mt][3] = *(const unsigned*)&Al[(r + 8) * LDS_STRIDE + kb + 8];
            }
#pragma unroll
            for (int nt = 0; nt < 8; nt++) {
                int nr = wn + nt * 8 + lr;
                int kb = kc + lk;
                unsigned bh[2], bl[2];
                bh[0] = *(const unsigned*)&Bh[nr * LDS_STRIDE + kb];
                bh[1] = *(const unsigned*)&Bh[nr * LDS_STRIDE + kb + 8];
                bl[0] = *(const unsigned*)&Bl[nr * LDS_STRIDE + kb];
                bl[1] = *(const unsigned*)&Bl[nr * LDS_STRIDE + kb + 8];
#pragma unroll
                for (int mt = 0; mt < 2; mt++) {
                    mma16816(acc[mt][nt], ah[mt], bh);
                    mma16816(acc[mt][nt], al[mt], bh);
                    mma16816(acc[mt][nt], ah[mt], bl);
                }
            }
        }
        __syncthreads();
    }

    // ---- epilogue ----
    const bool vtrans = (mode == 0) && (blockIdx.z == 2);
#pragma unroll
    for (int mt = 0; mt < 2; mt++) {
        int r1 = m0 + wm + mt * 16 + lr;
        int r2 = r1 + 8;
#pragma unroll
        for (int nt = 0; nt < 8; nt++) {
            int c = n0 + wn + nt * 8 + lk;
            if (mode == 0) {
                int b1 = r1 / Ss, s1 = r1 % Ss;
                int b2 = r2 / Ss, s2 = r2 % Ss;
                int h = c >> 6, jj = c & 63;
                if (vtrans) {
                    float* base1 = dst + ((size_t)(b1 * Hh + h) * DK) * Ss;
                    float* base2 = dst + ((size_t)(b2 * Hh + h) * DK) * Ss;
                    base1[(size_t)jj * Ss + s1]       = acc[mt][nt][0];
                    base1[(size_t)(jj + 1) * Ss + s1] = acc[mt][nt][1];
                    base2[(size_t)jj * Ss + s2]       = acc[mt][nt][2];
                    base2[(size_t)(jj + 1) * Ss + s2] = acc[mt][nt][3];
                } else {
                    float* p1 = dst + (((size_t)(b1 * Hh + h)) * Ss + s1) * DK + jj;
                    float* p2 = dst + (((size_t)(b2 * Hh + h)) * Ss + s2) * DK + jj;
                    p1[0] = acc[mt][nt][0]; p1[1] = acc[mt][nt][1];
                    p2[0] = acc[mt][nt][2]; p2[1] = acc[mt][nt][3];
                }
            } else {
                float* p1 = dst + (size_t)r1 * Dd + c;
                float* p2 = dst + (size_t)r2 * Dd + c;
                p1[0] = acc[mt][nt][0]; p1[1] = acc[mt][nt][1];
                p2[0] = acc[mt][nt][2]; p2[1] = acc[mt][nt][3];
            }
        }
    }
}

// ---------------------------------------------------------------------------
// RoPE in-place on q AND k ([b][h][s][d]) in a single launch.
// ---------------------------------------------------------------------------
__global__ void rope_kernel()
{
    const int TOTP = Bb * Hh * Ss * (DK / 2);   // per tensor
    int i = blockIdx.x * blockDim.x + threadIdx.x;
    float* t = (i < TOTP) ? g_q : g_k;
    if (i >= TOTP) i -= TOTP;
    int j2 = i & 31;
    int s = (i >> 5) & (Ss - 1);
    int bh = i >> 16;
    float* p = t + ((size_t)bh * Ss + s) * DK + 2 * j2;
    float freq = expf(-(2.0f * j2 / 64.0f) * 9.210340371976184f);
    float ang = (float)s * freq;
    float sn, cs;
    sincosf(ang, &sn, &cs);
    float x1 = p[0], x2 = p[1];
    p[0] = x1 * cs - x2 * sn;
    p[1] = x1 * sn + x2 * cs;
}

// ---------------------------------------------------------------------------
// Causal flash attention: 128-row Q blocks (8 warps), 64-col KV tiles,
// double-buffered smem with register-staged loads, ldmatrix fragment loads,
// split-bf16 MMA, base-2 online softmax, register-resident P.
// grid(16, 16, 4), block(256). Dynamic smem = 2 * 4 * 64*FST halves = 73728 B.
// ---------------------------------------------------------------------------
#define FST 72            // halves per smem row (64 + 8 pad); 144 B (16B mult.)
#define TILEH (64 * FST)  // halves per sub-array (K-hi/K-lo/V-hi/V-lo)
#define BUFH  (4 * TILEH) // halves per buffer

__global__ __launch_bounds__(256)
void flash_attn_mma()
{
    extern __shared__ __nv_bfloat16 fsm[];

    const int qi = blockIdx.x, h = blockIdx.y, b = blockIdx.z;
    const int tid = threadIdx.x, wid = tid >> 5, lane = tid & 31;
    const int lr = lane >> 2, lk2 = (lane & 3) * 2;
    const int wm = wid * 16;                 // warp rows [wm, wm+16) of 128
    const int bh = b * Hh + h;
    const float sc = 0.18033688011112043f;   // (1/sqrt(64)) * log2(e)

    // ldmatrix per-lane row-address offset (halves)
    const int Lsel = lane >> 3, Lrow = lane & 7;
    const int lmo = (Lrow + (Lsel >> 1) * 8) * FST + (Lsel & 1) * 8;

    const unsigned sbase = (unsigned)__cvta_generic_to_shared(fsm);

    // ---- Q fragments (registers, whole kernel) ----
    unsigned qh[4][4], ql[4][4];
    {
        const float* Qg = g_q + ((size_t)bh * Ss + qi * 128) * DK;
        int r0 = wm + lr, r1 = r0 + 8;
#pragma unroll
        for (int kc = 0; kc < 4; kc++) {
            int d0 = kc * 16 + lk2, d2 = d0 + 8;
            float2 q00 = *(const float2*)&Qg[r0 * DK + d0];
            float2 q10 = *(const float2*)&Qg[r1 * DK + d0];
            float2 q01 = *(const float2*)&Qg[r0 * DK + d2];
            float2 q11 = *(const float2*)&Qg[r1 * DK + d2];
            splitpack(q00.x, q00.y, qh[kc][0], ql[kc][0]);
            splitpack(q10.x, q10.y, qh[kc][1], ql[kc][1]);
            splitpack(q01.x, q01.y, qh[kc][2], ql[kc][2]);
            splitpack(q11.x, q11.y, qh[kc][3], ql[kc][3]);
        }
    }

    float Oa[8][4];
#pragma unroll
    for (int nt = 0; nt < 8; nt++)
#pragma unroll
        for (int q = 0; q < 4; q++) Oa[nt][q] = 0.0f;
    float m0 = -INFINITY, m1 = -INFINITY, l0 = 0.0f, l1 = 0.0f;

    const float* Kg = g_k + (size_t)bh * Ss * DK;
    const float* Vg = g_v + (size_t)bh * DK * Ss;

    const int jmax = 2 * qi + 1;
    const int wrmax = qi * 128 + wm + 15;    // warp's max global row

    // ---- stage tile j=0 into registers ----
    float4 kreg[4], vreg[4];
#pragma unroll
    for (int l = 0; l < 4; l++) {
        int fi = tid + l * 256;
        int row = fi >> 4, q4 = fi & 15;
        kreg[l] = *(const float4*)&Kg[(size_t)row * DK + q4 * 4];
        vreg[l] = *(const float4*)&Vg[(size_t)row * Ss + q4 * 4];
    }

    for (int j = 0; j <= jmax; ++j) {
        __nv_bfloat16* buf = fsm + (j & 1) * BUFH;

        // ---- store staged regs -> smem (split hi/lo) ----
#pragma unroll
        for (int l = 0; l < 4; l++) {
            int fi = tid + l * 256;
            int row = fi >> 4, q4 = fi & 15;
            int off = row * FST + q4 * 4;
            unsigned h0, lo0, h1, lo1;
            splitpack(kreg[l].x, kreg[l].y, h0, lo0);
            splitpack(kreg[l].z, kreg[l].w, h1, lo1);
            *(uint2*)&buf[off]         = make_uint2(h0, h1);
            *(uint2*)&buf[TILEH + off] = make_uint2(lo0, lo1);
            splitpack(vreg[l].x, vreg[l].y, h0, lo0);
            splitpack(vreg[l].z, vreg[l].w, h1, lo1);
            *(uint2*)&buf[2 * TILEH + off] = make_uint2(h0, h1);
            *(uint2*)&buf[3 * TILEH + off] = make_uint2(lo0, lo1);
        }
        __syncthreads();

        // ---- issue next tile's gmem loads (overlap with MMA) ----
        if (j < jmax) {
#pragma unroll
            for (int l = 0; l < 4; l++) {
                int fi = tid + l * 256;
                int row = fi >> 4, q4 = fi & 15;
                kreg[l] = *(const float4*)&Kg[(size_t)((j + 1) * 64 + row) * DK + q4 * 4];
                vreg[l] = *(const float4*)&Vg[(size_t)row * Ss + (j + 1) * 64 + q4 * 4];
            }
        }

        // ---- warp-uniform skip of fully-masked tiles ----
        if (j * 64 <= wrmax) {
            const unsigned bufb = sbase + (unsigned)((j & 1) * BUFH) * 2u;
            const unsigned kh_b = bufb;
            const unsigned kl_b = bufb + TILEH * 2u;
            const unsigned vh_b = bufb + 2u * TILEH * 2u;
            const unsigned vl_b = bufb + 3u * TILEH * 2u;

            // ---- S = Q K^T ----
            float sa[8][4];
#pragma unroll
            for (int nt = 0; nt < 8; nt++)
#pragma unroll
                for (int q = 0; q < 4; q++) sa[nt][q] = 0.0f;

#pragma unroll
            for (int kc = 0; kc < 4; kc++) {
#pragma unroll
                for (int nt2 = 0; nt2 < 4; nt2++) {
                    unsigned off2 = (unsigned)(nt2 * 16 * FST + kc * 16 + lmo) * 2u;
                    unsigned kh0, kh1, kh2, kh3, kl0, kl1, kl2, kl3;
                    ldsm4(kh0, kh1, kh2, kh3, kh_b + off2);
                    ldsm4(kl0, kl1, kl2, kl3, kl_b + off2);
                    unsigned Bh0[2] = {kh0, kh1}, Bh1[2] = {kh2, kh3};
                    unsigned Bl0[2] = {kl0, kl1}, Bl1[2] = {kl2, kl3};
                    mma16816(sa[2 * nt2],     qh[kc], Bh0);
                    mma16816(sa[2 * nt2],     ql[kc], Bh0);
                    mma16816(sa[2 * nt2],     qh[kc], Bl0);
                    mma16816(sa[2 * nt2 + 1], qh[kc], Bh1);
                    mma16816(sa[2 * nt2 + 1], ql[kc], Bh1);
                    mma16816(sa[2 * nt2 + 1], qh[kc], Bl1);
                }
            }

            // ---- scale + causal mask ----
            const bool diag = (j * 64 + 63 > qi * 128 + wm);
            int rg0 = qi * 128 + wm + lr, rg1 = rg0 + 8;
#pragma unroll
            for (int nt = 0; nt < 8; nt++) {
                int cg = j * 64 + nt * 8 + lk2;
                if (diag) {
                    sa[nt][0] = (cg     > rg0) ? -INFINITY : sa[nt][0] * sc;
                    sa[nt][1] = (cg + 1 > rg0) ? -INFINITY : sa[nt][1] * sc;
                    sa[nt][2] = (cg     > rg1) ? -INFINITY : sa[nt][2] * sc;
                    sa[nt][3] = (cg + 1 > rg1) ? -INFINITY : sa[nt][3] * sc;
                } else {
                    sa[nt][0] *= sc; sa[nt][1] *= sc;
                    sa[nt][2] *= sc; sa[nt][3] *= sc;
                }
            }

            // ---- row max over quad ----
            float rm0 = -INFINITY, rm1 = -INFINITY;
#pragma unroll
            for (int nt = 0; nt < 8; nt++) {
                rm0 = fmaxf(rm0, fmaxf(sa[nt][0], sa[nt][1]));
                rm1 = fmaxf(rm1, fmaxf(sa[nt][2], sa[nt][3]));
            }
            rm0 = fmaxf(rm0, __shfl_xor_sync(0xffffffffu, rm0, 1));
            rm0 = fmaxf(rm0, __shfl_xor_sync(0xffffffffu, rm0, 2));
            rm1 = fmaxf(rm1, __shfl_xor_sync(0xffffffffu, rm1, 1));
            rm1 = fmaxf(rm1, __shfl_xor_sync(0xffffffffu, rm1, 2));
            float mn0 = fmaxf(m0, rm0), mn1 = fmaxf(m1, rm1);

            // ---- exp2 + pack P ----
            unsigned pha[8], phb[8], pla[8], plb[8];
            float rs0 = 0.0f, rs1 = 0.0f;
#pragma unroll
            for (int nt = 0; nt < 8; nt++) {
                float p0 = exp2f(sa[nt][0] - mn0);
                float p1 = exp2f(sa[nt][1] - mn0);
                float p2 = exp2f(sa[nt][2] - mn1);
                float p3 = exp2f(sa[nt][3] - mn1);
                rs0 += p0 + p1;
                rs1 += p2 + p3;
                splitpack(p0, p1, pha[nt], pla[nt]);
                splitpack(p2, p3, phb[nt], plb[nt]);
            }
            rs0 += __shfl_xor_sync(0xffffffffu, rs0, 1);
            rs0 += __shfl_xor_sync(0xffffffffu, rs0, 2);
            rs1 += __shfl_xor_sync(0xffffffffu, rs1, 1);
            rs1 += __shfl_xor_sync(0xffffffffu, rs1, 2);

            float f0 = exp2f(m0 - mn0), f1 = exp2f(m1 - mn1);
            l0 = l0 * f0 + rs0;
            l1 = l1 * f1 + rs1;
            m0 = mn0; m1 = mn1;
#pragma unroll
            for (int nt = 0; nt < 8; nt++) {
                Oa[nt][0] *= f0; Oa[nt][1] *= f0;
                Oa[nt][2] *= f1; Oa[nt][3] *= f1;
            }

            // ---- O += P V ----
#pragma unroll
            for (int kc = 0; kc < 4; kc++) {
                unsigned Aph[4] = { pha[2 * kc], phb[2 * kc], pha[2 * kc + 1], phb[2 * kc + 1] };
                unsigned Apl[4] = { pla[2 * kc], plb[2 * kc], pla[2 * kc + 1], plb[2 * kc + 1] };
#pragma unroll
                for (int nt2 = 0; nt2 < 4; nt2++) {
                    unsigned off2 = (unsigned)(nt2 * 16 * FST + kc * 16 + lmo) * 2u;
                    unsigned vh0, vh1, vh2, vh3, vl0, vl1, vl2, vl3;
                    ldsm4(vh0, vh1, vh2, vh3, vh_b + off2);
                    ldsm4(vl0, vl1, vl2, vl3, vl_b + off2);
                    unsigned Vh0[2] = {vh0, vh1}, Vh1[2] = {vh2, vh3};
                    unsigned Vl0[2] = {vl0, vl1}, Vl1[2] = {vl2, vl3};
                    mma16816(Oa[2 * nt2],     Aph, Vh0);
                    mma16816(Oa[2 * nt2],     Apl, Vh0);
                    mma16816(Oa[2 * nt2],     Aph, Vl0);
                    mma16816(Oa[2 * nt2 + 1], Aph, Vh1);
                    mma16816(Oa[2 * nt2 + 1], Apl, Vh1);
                    mma16816(Oa[2 * nt2 + 1], Aph, Vl1);
                }
            }
        }
        // no trailing sync: next iter writes the OTHER buffer; iter j+2's
        // writes to THIS buffer are ordered after sync(j+1), which follows
        // everyone's reads here.
    }

    // ---- normalize + write [b][s][h*64+d] ----
    float inv0 = 1.0f / l0, inv1 = 1.0f / l1;
    int s0 = qi * 128 + wm + lr, s1 = s0 + 8;
#pragma unroll
    for (int nt = 0; nt < 8; nt++) {
        int d = nt * 8 + lk2;
        float2 o0 = make_float2(Oa[nt][0] * inv0, Oa[nt][1] * inv0);
        float2 o1 = make_float2(Oa[nt][2] * inv1, Oa[nt][3] * inv1);
        *(float2*)&g_att[((size_t)b * Ss + s0) * Dd + h * DK + d] = o0;
        *(float2*)&g_att[((size_t)b * Ss + s1) * Dd + h * DK + d] = o1;
    }
}

// ---------------------------------------------------------------------------
extern "C" void kernel_launch(void* const* d_in, const int* in_sizes, int n_in,
                              void* d_out, int out_size)
{
    const float* x  = (const float*)d_in[0];
    const float* wq = (const float*)d_in[1];
    const float* wk = (const float*)d_in[2];
    const float* wv = (const float*)d_in[3];
    const float* wo = (const float*)d_in[4];
    float* out = (float*)d_out;

    (void)in_sizes; (void)n_in; (void)out_size;

    const int FLASH_SMEM = 2 * BUFH * (int)sizeof(__nv_bfloat16);   // 73728
    cudaFuncSetAttribute(flash_attn_mma, cudaFuncAttributeMaxDynamicSharedMemorySize, FLASH_SMEM);

    // 1) QKV projections (tensor cores, bf16 split); V stored transposed
    gemm_bf16s<<<dim3(Mm / 128, Dd / 128, 3), 256>>>(x, wq, wk, wv, nullptr, 0);

    // 2) RoPE on q and k (single launch)
    {
        const int TOTP = Bb * Hh * Ss * (DK / 2);
        rope_kernel<<<(2 * TOTP) / 256, 256>>>();
    }

    // 3) causal flash attention (tensor cores, ldmatrix, double-buffered)
    flash_attn_mma<<<dim3(Ss / 128, Hh, Bb), 256, FLASH_SMEM>>>();

    // 4) output projection (tensor cores, bf16 split; A = g_att in-kernel)
    gemm_bf16s<<<dim3(Mm / 128, Dd / 128, 1), 256>>>(nullptr, wo, nullptr, nullptr, out, 1);
}